// round 11
// baseline (speedup 1.0000x reference)
#include <cuda_runtime.h>
#include <cuda_bf16.h>
#include <cuda_fp16.h>
#include <cstdint>
#include <cstddef>

// ---------------- problem constants ----------------
#define NHEAD 8
#define HD 32
#define NTOK 256
#define BATCH 256
#define DIMC 256
#define NGROUP 64
#define PD 16
#define LREL 961
#define QSCALE 0.17677669529663687f

// ---------------- device scratch ----------------
__device__ float g_qh[BATCH * NTOK * DIMC];
__device__ float g_kv[BATCH * NTOK * 2 * DIMC];
__device__ float g_pos[LREL * NHEAD];
__device__ float g_rpb[NHEAD * NTOK * NTOK];
__device__ uint32_t g_qwhi[256 * 128],  g_qwlo[256 * 128];
__device__ uint32_t g_kvwhi[512 * 128], g_kvwlo[512 * 128];
__device__ uint32_t g_pwhi[256 * 128],  g_pwlo[256 * 128];
__device__ float g_qbs[256];
__device__ uint32_t g_xhi[(size_t)BATCH * NTOK * 128];
__device__ uint32_t g_xlo[(size_t)BATCH * NTOK * 128];

// ---------------- helpers ----------------
__device__ __forceinline__ uint32_t smem_u32(const void* p) {
    uint32_t a;
    asm("{ .reg .u64 t; cvta.to.shared.u64 t, %1; cvt.u32.u64 %0, t; }" : "=r"(a) : "l"(p));
    return a;
}
__device__ __forceinline__ void cp16(uint32_t saddr, const void* g) {
    asm volatile("cp.async.cg.shared.global [%0], [%1], 16;" :: "r"(saddr), "l"(g) : "memory");
}
__device__ __forceinline__ void cp_commit() { asm volatile("cp.async.commit_group;" ::: "memory"); }
__device__ __forceinline__ void cp_wait0() { asm volatile("cp.async.wait_group 0;" ::: "memory"); }
__device__ __forceinline__ void cp_wait1() { asm volatile("cp.async.wait_group 1;" ::: "memory"); }

__device__ __forceinline__ void ldsm_x4(uint32_t* r, uint32_t a) {
    asm volatile("ldmatrix.sync.aligned.m8n8.x4.shared.b16 {%0,%1,%2,%3}, [%4];"
        : "=r"(r[0]), "=r"(r[1]), "=r"(r[2]), "=r"(r[3]) : "r"(a));
}
__device__ __forceinline__ void ldsm_x4_t(uint32_t* r, uint32_t a) {
    asm volatile("ldmatrix.sync.aligned.m8n8.x4.trans.shared.b16 {%0,%1,%2,%3}, [%4];"
        : "=r"(r[0]), "=r"(r[1]), "=r"(r[2]), "=r"(r[3]) : "r"(a));
}

__device__ __forceinline__ void pack_bf16_pair(float x, float y, uint32_t& hi, uint32_t& lo) {
    __nv_bfloat16 hx = __float2bfloat16_rn(x);
    __nv_bfloat16 hy = __float2bfloat16_rn(y);
    float rx = x - __bfloat162float(hx);
    float ry = y - __bfloat162float(hy);
    __nv_bfloat16 lx = __float2bfloat16_rn(rx);
    __nv_bfloat16 ly = __float2bfloat16_rn(ry);
    hi = ((uint32_t)__bfloat16_as_ushort(hy) << 16) | (uint32_t)__bfloat16_as_ushort(hx);
    lo = ((uint32_t)__bfloat16_as_ushort(ly) << 16) | (uint32_t)__bfloat16_as_ushort(lx);
}
__device__ __forceinline__ void mma_bf16(float* d, const uint32_t* a, const uint32_t* b) {
    asm volatile("mma.sync.aligned.m16n8k16.row.col.f32.bf16.bf16.f32 "
        "{%0,%1,%2,%3}, {%4,%5,%6,%7}, {%8,%9}, {%0,%1,%2,%3};"
        : "+f"(d[0]), "+f"(d[1]), "+f"(d[2]), "+f"(d[3])
        : "r"(a[0]), "r"(a[1]), "r"(a[2]), "r"(a[3]), "r"(b[0]), "r"(b[1]));
}
__device__ __forceinline__ void mma_f16(float* d, const uint32_t* a, const uint32_t* b) {
    asm volatile("mma.sync.aligned.m16n8k16.row.col.f32.f16.f16.f32 "
        "{%0,%1,%2,%3}, {%4,%5,%6,%7}, {%8,%9}, {%0,%1,%2,%3};"
        : "+f"(d[0]), "+f"(d[1]), "+f"(d[2]), "+f"(d[3])
        : "r"(a[0]), "r"(a[1]), "r"(a[2]), "r"(a[3]), "r"(b[0]), "r"(b[1]));
}

// ---------------- weight pre-conversion ----------------
__global__ void conv_w_kernel(const float* __restrict__ qw, const float* __restrict__ kvw,
                              const float* __restrict__ pw, const float* __restrict__ qb) {
    int idx = blockIdx.x * 256 + threadIdx.x;
    int row = idx >> 7, p = idx & 127;
    const float* src;
    uint32_t *dh, *dl;
    float sc = 1.f;
    if (row < 256)      { src = qw + row * 256;          dh = g_qwhi + row * 128 + p;          dl = g_qwlo + row * 128 + p;          sc = QSCALE; }
    else if (row < 768) { int r = row - 256; src = kvw + r * 256; dh = g_kvwhi + r * 128 + p;  dl = g_kvwlo + r * 128 + p; }
    else                { int r = row - 768; src = pw + r * 256;  dh = g_pwhi + r * 128 + p;   dl = g_pwlo + r * 128 + p; }
    uint32_t hi, lo;
    pack_bf16_pair(src[2 * p] * sc, src[2 * p + 1] * sc, hi, lo);
    *dh = hi; *dl = lo;
    if (idx < 256) g_qbs[idx] = qb[idx] * QSCALE;
}

// ---------------- pos-bias MLP ----------------
__device__ __forceinline__ void ln16(float* x, const float* g, const float* b) {
    float m = 0.f;
#pragma unroll
    for (int i = 0; i < PD; i++) m += x[i];
    m *= (1.0f / PD);
    float v = 0.f;
#pragma unroll
    for (int i = 0; i < PD; i++) { float d = x[i] - m; v += d * d; }
    v *= (1.0f / PD);
    float inv = rsqrtf(v + 1e-5f);
#pragma unroll
    for (int i = 0; i < PD; i++) x[i] = (x[i] - m) * inv * g[i] + b[i];
}

__global__ void pos_mlp_kernel(const float* __restrict__ pp_w, const float* __restrict__ pp_b,
                               const float* __restrict__ ln1_g, const float* __restrict__ ln1_b,
                               const float* __restrict__ l1_w,  const float* __restrict__ l1_b,
                               const float* __restrict__ ln2_g, const float* __restrict__ ln2_b,
                               const float* __restrict__ l2_w,  const float* __restrict__ l2_b,
                               const float* __restrict__ ln3_g, const float* __restrict__ ln3_b,
                               const float* __restrict__ l3_w,  const float* __restrict__ l3_b) {
    int p = blockIdx.x * blockDim.x + threadIdx.x;
    if (p >= LREL) return;
    float b0 = (float)(p / 31 - 15);
    float b1 = (float)(p % 31 - 15);
    float x[PD], y[PD];
#pragma unroll
    for (int o = 0; o < PD; o++) x[o] = b0 * pp_w[o * 2 + 0] + b1 * pp_w[o * 2 + 1] + pp_b[o];
    ln16(x, ln1_g, ln1_b);
#pragma unroll
    for (int o = 0; o < PD; o++) {
        float s = l1_b[o];
#pragma unroll
        for (int i = 0; i < PD; i++) s += fmaxf(x[i], 0.f) * l1_w[o * PD + i];
        y[o] = s;
    }
#pragma unroll
    for (int o = 0; o < PD; o++) x[o] = y[o];
    ln16(x, ln2_g, ln2_b);
#pragma unroll
    for (int o = 0; o < PD; o++) {
        float s = l2_b[o];
#pragma unroll
        for (int i = 0; i < PD; i++) s += fmaxf(x[i], 0.f) * l2_w[o * PD + i];
        y[o] = s;
    }
#pragma unroll
    for (int o = 0; o < PD; o++) x[o] = y[o];
    ln16(x, ln3_g, ln3_b);
#pragma unroll
    for (int h = 0; h < NHEAD; h++) {
        float s = l3_b[h];
#pragma unroll
        for (int i = 0; i < PD; i++) s += fmaxf(x[i], 0.f) * l3_w[h * PD + i];
        g_pos[p * NHEAD + h] = s;
    }
}

__global__ void rpb_fill_kernel() {
    int i = blockIdx.x * 256 + threadIdx.x;
    int h = i >> 16;
    int rem = i & 65535;
    int n = rem >> 8;
    int m = rem & 255;
    int di = (n >> 4) - (m >> 4) + 15;
    int dj = (n & 15) - (m & 15) + 15;
    g_rpb[i] = g_pos[(di * 31 + dj) * NHEAD + h];
}

// ---------------- GEMM infrastructure ----------------
#define SWZ(r, c) (((r) << 4) + ((c) ^ ((((r) >> 1) & 3) << 2)))
#define GSW_TILE 2048
#define GSW_STAGE 8192

__device__ __forceinline__ void fill_packed_async(uint32_t sbase, int st, int baseoff, int tid,
                                                  const uint32_t* Whi, const uint32_t* Wlo,
                                                  int r0, int kc) {
#pragma unroll
    for (int i = 0; i < 2; i++) {
        int idx = tid * 2 + i;
        int row = idx >> 2, c4 = (idx & 3) << 2;
        uint32_t off = (uint32_t)((st * GSW_STAGE + baseoff + SWZ(row, c4)) * 4);
        size_t gidx = (size_t)(r0 + row) * 128 + kc * 16 + c4;
        cp16(sbase + off, Whi + gidx);
        cp16(sbase + off + GSW_TILE * 4, Wlo + gidx);
    }
}

// ldmatrix-based compute: 24 LDSM per chunk (was 96 scalar LDS)
__device__ __forceinline__ void gemm_compute(uint32_t sstage, int wm, int wn, int lane,
                                             float acc[4][4][4]) {
    int arow = (lane & 7) + ((lane >> 3) & 1) * 8;
    int acsel = ((lane >> 4) & 1) * 4;
    int brow = lane & 7;
    int bcsel = (lane >> 3) * 4;
    uint32_t bh[4][4], bl[4][4];
#pragma unroll
    for (int nt = 0; nt < 4; nt++) {
        uint32_t idx = SWZ(wn + nt * 8 + brow, bcsel);
        ldsm_x4(bh[nt], sstage + (2 * GSW_TILE + idx) * 4);
        ldsm_x4(bl[nt], sstage + (3 * GSW_TILE + idx) * 4);
    }
#pragma unroll
    for (int mt = 0; mt < 4; mt++) {
        uint32_t ah[2][4], al[2][4];
#pragma unroll
        for (int ks = 0; ks < 2; ks++) {
            uint32_t idx = SWZ(wm + mt * 16 + arow, ks * 8 + acsel);
            ldsm_x4(ah[ks], sstage + idx * 4);
            ldsm_x4(al[ks], sstage + (GSW_TILE + idx) * 4);
        }
#pragma unroll
        for (int nt = 0; nt < 4; nt++)
#pragma unroll
            for (int ks = 0; ks < 2; ks++) {
                mma_bf16(acc[mt][nt], ah[ks], &bh[nt][ks * 2]);
                mma_bf16(acc[mt][nt], ah[ks], &bl[nt][ks * 2]);
                mma_bf16(acc[mt][nt], al[ks], &bh[nt][ks * 2]);
            }
    }
}

// ---------------- merged Q + KV projection GEMM ----------------
__global__ __launch_bounds__(256, 2)
void gemm_qkv(const float* __restrict__ q, const float* __restrict__ kfeat,
              const float* __restrict__ kv_b) {
    extern __shared__ uint32_t gsm[];
    uint32_t sbase = smem_u32(gsm);
    int tid = threadIdx.x, lane = tid & 31, wid = tid >> 5;
    int bx = blockIdx.x, m0 = blockIdx.y * 128;
    const float* A; const uint32_t *Whi, *Wlo; float* C; const float* bias; int Ncols, n0;
    if (bx < 2) { A = q;     Whi = g_qwhi;  Wlo = g_qwlo;  C = g_qh; bias = g_qbs; Ncols = 256; n0 = bx * 128; }
    else        { A = kfeat; Whi = g_kvwhi; Wlo = g_kvwlo; C = g_kv; bias = kv_b;  Ncols = 512; n0 = (bx - 2) * 128; }

    int wm = (wid >> 2) * 64, wn = (wid & 3) * 32;
    int g = lane >> 2, tg = lane & 3;
    int lrow = tid >> 3, lc4 = (tid & 7) * 4, lp = lc4 >> 1;

    float acc[4][4][4];
#pragma unroll
    for (int a = 0; a < 4; a++)
#pragma unroll
        for (int bq = 0; bq < 4; bq++)
#pragma unroll
            for (int c = 0; c < 4; c++) acc[a][bq][c] = 0.f;

    {
        uint32_t* st0 = gsm;
#pragma unroll
        for (int it = 0; it < 4; it++) {
            int row = it * 32 + lrow;
            float4 a4 = *(const float4*)(A + (size_t)(m0 + row) * 256 + lc4);
            uint32_t h0, l0, h1, l1;
            pack_bf16_pair(a4.x, a4.y, h0, l0); pack_bf16_pair(a4.z, a4.w, h1, l1);
            int p0 = SWZ(row, lp);
            st0[p0] = h0; st0[p0 + 1] = h1;
            st0[GSW_TILE + p0] = l0; st0[GSW_TILE + p0 + 1] = l1;
        }
        fill_packed_async(sbase, 0, 2 * GSW_TILE, tid, Whi, Wlo, n0, 0);
        cp_commit();
    }

    for (int kc = 0; kc < 8; kc++) {
        int s = kc & 1;
        bool pre = (kc + 1 < 8);
        float4 a4[4];
        if (pre) {
#pragma unroll
            for (int it = 0; it < 4; it++) {
                int row = it * 32 + lrow;
                a4[it] = *(const float4*)(A + (size_t)(m0 + row) * 256 + (kc + 1) * 32 + lc4);
            }
            fill_packed_async(sbase, s ^ 1, 2 * GSW_TILE, tid, Whi, Wlo, n0, kc + 1);
            cp_commit();
            cp_wait1();
        } else {
            cp_wait0();
        }
        __syncthreads();
        gemm_compute(sbase + s * GSW_STAGE * 4, wm, wn, lane, acc);
        if (pre) {
            uint32_t* stn = gsm + (s ^ 1) * GSW_STAGE;
#pragma unroll
            for (int it = 0; it < 4; it++) {
                int row = it * 32 + lrow;
                uint32_t h0, l0, h1, l1;
                pack_bf16_pair(a4[it].x, a4[it].y, h0, l0); pack_bf16_pair(a4[it].z, a4[it].w, h1, l1);
                int p0 = SWZ(row, lp);
                stn[p0] = h0; stn[p0 + 1] = h1;
                stn[GSW_TILE + p0] = l0; stn[GSW_TILE + p0 + 1] = l1;
            }
        }
        __syncthreads();
    }

#pragma unroll
    for (int mt = 0; mt < 4; mt++) {
        int r0 = m0 + wm + mt * 16 + g;
#pragma unroll
        for (int nt = 0; nt < 4; nt++) {
            int col = n0 + wn + nt * 8 + 2 * tg;
            float bb0 = bias[col], bb1 = bias[col + 1];
            float2 v0, v1;
            v0.x = acc[mt][nt][0] + bb0; v0.y = acc[mt][nt][1] + bb1;
            v1.x = acc[mt][nt][2] + bb0; v1.y = acc[mt][nt][3] + bb1;
            *(float2*)(C + (size_t)r0 * Ncols + col) = v0;
            *(float2*)(C + (size_t)(r0 + 8) * Ncols + col) = v1;
        }
    }
}

// ---------------- output projection GEMM ----------------
__global__ __launch_bounds__(256, 2)
void gemm_proj(const float* __restrict__ proj_b, float* __restrict__ out) {
    extern __shared__ uint32_t gsm[];
    uint32_t sbase = smem_u32(gsm);
    int tid = threadIdx.x, lane = tid & 31, wid = tid >> 5;
    int m0 = blockIdx.y * 128, n0 = blockIdx.x * 128;
    int wm = (wid >> 2) * 64, wn = (wid & 3) * 32;
    int g = lane >> 2, tg = lane & 3;

    float acc[4][4][4];
#pragma unroll
    for (int a = 0; a < 4; a++)
#pragma unroll
        for (int bq = 0; bq < 4; bq++)
#pragma unroll
            for (int c = 0; c < 4; c++) acc[a][bq][c] = 0.f;

    fill_packed_async(sbase, 0, 0, tid, g_xhi, g_xlo, m0, 0);
    fill_packed_async(sbase, 0, 2 * GSW_TILE, tid, g_pwhi, g_pwlo, n0, 0);
    cp_commit();

    for (int kc = 0; kc < 8; kc++) {
        int s = kc & 1;
        bool pre = (kc + 1 < 8);
        if (pre) {
            fill_packed_async(sbase, s ^ 1, 0, tid, g_xhi, g_xlo, m0, kc + 1);
            fill_packed_async(sbase, s ^ 1, 2 * GSW_TILE, tid, g_pwhi, g_pwlo, n0, kc + 1);
            cp_commit();
            cp_wait1();
        } else {
            cp_wait0();
        }
        __syncthreads();
        gemm_compute(sbase + s * GSW_STAGE * 4, wm, wn, lane, acc);
        __syncthreads();
    }

#pragma unroll
    for (int mt = 0; mt < 4; mt++) {
        int r0 = m0 + wm + mt * 16 + g;
#pragma unroll
        for (int nt = 0; nt < 4; nt++) {
            int col = n0 + wn + nt * 8 + 2 * tg;
            float bb0 = proj_b[col], bb1 = proj_b[col + 1];
            float2 v0, v1;
            v0.x = acc[mt][nt][0] + bb0; v0.y = acc[mt][nt][1] + bb1;
            v1.x = acc[mt][nt][2] + bb0; v1.y = acc[mt][nt][3] + bb1;
            *(float2*)(out + (size_t)r0 * 256 + col) = v0;
            *(float2*)(out + (size_t)(r0 + 8) * 256 + col) = v1;
        }
    }
}

// ---------------- fused attention on tensor cores (ldmatrix) ----------------
// K: bf16 hi/lo [key][u32 k-pair] stride 20.  Q: same, 128 rows (pre-scaled).
// V: f16 [key][u32 dim-pair] stride 20 (read via ldmatrix.trans).
#define KSTR 20
#define A_KHI 0
#define A_KLO 5120
#define A_QHI 10240
#define A_QLO 12800
#define A_VT  15360
#define A_TOT 20480
__global__ __launch_bounds__(256, 1)
void attn_kernel(const float* __restrict__ mask) {
    extern __shared__ uint32_t smu[];
    uint32_t sb = smem_u32(smu);
    uint32_t* Khi = smu + A_KHI;
    uint32_t* Klo = smu + A_KLO;
    uint32_t* Qhi = smu + A_QHI;
    uint32_t* Qlo = smu + A_QLO;
    uint32_t* Vt  = smu + A_VT;

    int tid = threadIdx.x, lane = tid & 31, w = tid >> 5;
    int r0 = blockIdx.x * 128, h = blockIdx.y, b = blockIdx.z;
    int g = lane >> 2, tg = lane & 3;

    {
        int key8 = tid >> 3, d4 = (tid & 7) * 4;
#pragma unroll
        for (int it = 0; it < 8; it++) {
            int key = it * 32 + key8;
            const float* src = g_kv + (size_t)(b * NTOK + key) * (2 * DIMC) + h * HD + d4;
            float4 kx = *(const float4*)src;
            float4 vx = *(const float4*)(src + DIMC);
            uint32_t h0, l0, h1, l1;
            pack_bf16_pair(kx.x, kx.y, h0, l0);
            pack_bf16_pair(kx.z, kx.w, h1, l1);
            int kb = key * KSTR + (d4 >> 1);
            Khi[kb] = h0; Khi[kb + 1] = h1;
            Klo[kb] = l0; Klo[kb + 1] = l1;
            __half2 v01 = __floats2half2_rn(vx.x, vx.y);
            __half2 v23 = __floats2half2_rn(vx.z, vx.w);
            Vt[kb] = *(uint32_t*)&v01;
            Vt[kb + 1] = *(uint32_t*)&v23;
        }
#pragma unroll
        for (int it = 0; it < 4; it++) {
            int row = it * 32 + key8;
            float4 qx = *(const float4*)(g_qh + (size_t)(b * NTOK + r0 + row) * DIMC + h * HD + d4);
            uint32_t h0, l0, h1, l1;
            pack_bf16_pair(qx.x, qx.y, h0, l0);
            pack_bf16_pair(qx.z, qx.w, h1, l1);
            int qb = row * KSTR + (d4 >> 1);
            Qhi[qb] = h0; Qhi[qb + 1] = h1;
            Qlo[qb] = l0; Qlo[qb + 1] = l1;
        }
    }
    __syncthreads();

    int wm = w * 16;

    // Q fragments via ldmatrix
    int arow = (lane & 7) + ((lane >> 3) & 1) * 8;
    int acsel = ((lane >> 4) & 1) * 4;
    uint32_t qh_[2][4], ql_[2][4];
#pragma unroll
    for (int ks = 0; ks < 2; ks++) {
        uint32_t idx = (uint32_t)((wm + arow) * KSTR + ks * 8 + acsel);
        ldsm_x4(qh_[ks], sb + (A_QHI + idx) * 4);
        ldsm_x4(ql_[ks], sb + (A_QLO + idx) * 4);
    }

    // QK^T
    int brow = lane & 7, bcsel = (lane >> 3) * 4;
    float sc[32][4];
#pragma unroll
    for (int j = 0; j < 32; j++) { sc[j][0] = 0.f; sc[j][1] = 0.f; sc[j][2] = 0.f; sc[j][3] = 0.f; }
#pragma unroll
    for (int j = 0; j < 32; j++) {
        uint32_t idx = (uint32_t)((j * 8 + brow) * KSTR + bcsel);
        uint32_t kh4[4], kl4[4];
        ldsm_x4(kh4, sb + (A_KHI + idx) * 4);
        ldsm_x4(kl4, sb + (A_KLO + idx) * 4);
        mma_bf16(sc[j], qh_[0], kh4);     mma_bf16(sc[j], qh_[0], kl4);     mma_bf16(sc[j], ql_[0], kh4);
        mma_bf16(sc[j], qh_[1], kh4 + 2); mma_bf16(sc[j], qh_[1], kl4 + 2); mma_bf16(sc[j], ql_[1], kh4 + 2);
    }

    int R0 = r0 + wm + g;
    const float* rpbR = g_rpb + ((size_t)h * NTOK + R0) * NTOK;
    const float* mkR  = mask + ((size_t)(b & (NGROUP - 1)) * NTOK + R0) * NTOK;
#pragma unroll
    for (int j = 0; j < 32; j++) {
        int c = j * 8 + 2 * tg;
        float2 r0v = *(const float2*)(rpbR + c);
        float2 r1v = *(const float2*)(rpbR + 8 * NTOK + c);
        float2 m0v = *(const float2*)(mkR + c);
        float2 m1v = *(const float2*)(mkR + 8 * NTOK + c);
        sc[j][0] += r0v.x + m0v.x; sc[j][1] += r0v.y + m0v.y;
        sc[j][2] += r1v.x + m1v.x; sc[j][3] += r1v.y + m1v.y;
    }

    float mx0 = -1e30f, mx1 = -1e30f;
#pragma unroll
    for (int j = 0; j < 32; j++) {
        mx0 = fmaxf(mx0, fmaxf(sc[j][0], sc[j][1]));
        mx1 = fmaxf(mx1, fmaxf(sc[j][2], sc[j][3]));
    }
    mx0 = fmaxf(mx0, __shfl_xor_sync(0xffffffffu, mx0, 1));
    mx0 = fmaxf(mx0, __shfl_xor_sync(0xffffffffu, mx0, 2));
    mx1 = fmaxf(mx1, __shfl_xor_sync(0xffffffffu, mx1, 1));
    mx1 = fmaxf(mx1, __shfl_xor_sync(0xffffffffu, mx1, 2));

    uint32_t pf[16][4];
    float sum0 = 0.f, sum1 = 0.f;
#pragma unroll
    for (int jj = 0; jj < 16; jj++) {
        __half2 e0 = h2exp(__floats2half2_rn(sc[2 * jj][0] - mx0, sc[2 * jj][1] - mx0));
        __half2 e1 = h2exp(__floats2half2_rn(sc[2 * jj][2] - mx1, sc[2 * jj][3] - mx1));
        __half2 e2 = h2exp(__floats2half2_rn(sc[2 * jj + 1][0] - mx0, sc[2 * jj + 1][1] - mx0));
        __half2 e3 = h2exp(__floats2half2_rn(sc[2 * jj + 1][2] - mx1, sc[2 * jj + 1][3] - mx1));
        pf[jj][0] = *(uint32_t*)&e0;
        pf[jj][1] = *(uint32_t*)&e1;
        pf[jj][2] = *(uint32_t*)&e2;
        pf[jj][3] = *(uint32_t*)&e3;
        float2 f0 = __half22float2(e0), f1 = __half22float2(e1);
        float2 f2 = __half22float2(e2), f3 = __half22float2(e3);
        sum0 += f0.x + f0.y + f2.x + f2.y;
        sum1 += f1.x + f1.y + f3.x + f3.y;
    }
    sum0 += __shfl_xor_sync(0xffffffffu, sum0, 1);
    sum0 += __shfl_xor_sync(0xffffffffu, sum0, 2);
    sum1 += __shfl_xor_sync(0xffffffffu, sum1, 1);
    sum1 += __shfl_xor_sync(0xffffffffu, sum1, 2);
    float inv0 = 1.0f / sum0, inv1 = 1.0f / sum1;

    // P @ V via ldmatrix.trans (V stored [key][dim])
    size_t ro0 = (size_t)(b * NTOK + R0) * 128;
    size_t ro1 = ro0 + 8 * 128;
#pragma unroll
    for (int dt = 0; dt < 4; dt++) {
        float ob[4] = {0.f, 0.f, 0.f, 0.f};
#pragma unroll
        for (int p = 0; p < 8; p++) {
            uint32_t v4[4];
            uint32_t idx = (uint32_t)((p * 32 + lane) * KSTR + dt * 4);
            ldsm_x4_t(v4, sb + (A_VT + idx) * 4);
            mma_f16(ob, pf[p * 2], v4);
            mma_f16(ob, pf[p * 2 + 1], v4 + 2);
        }
        int pc = h * 16 + dt * 4 + tg;
        uint32_t hi0, lo0, hi1, lo1;
        pack_bf16_pair(ob[0] * inv0, ob[1] * inv0, hi0, lo0);
        pack_bf16_pair(ob[2] * inv1, ob[3] * inv1, hi1, lo1);
        g_xhi[ro0 + pc] = hi0; g_xlo[ro0 + pc] = lo0;
        g_xhi[ro1 + pc] = hi1; g_xlo[ro1 + pc] = lo1;
    }
}

// ---------------- launch ----------------
extern "C" void kernel_launch(void* const* d_in, const int* in_sizes, int n_in,
                              void* d_out, int out_size) {
    const float* q      = (const float*)d_in[0];
    const float* k      = (const float*)d_in[1];
    const float* mask   = (const float*)d_in[2];
    const float* q_w    = (const float*)d_in[3];
    const float* q_b    = (const float*)d_in[4];
    const float* kv_w   = (const float*)d_in[5];
    const float* kv_b   = (const float*)d_in[6];
    const float* proj_w = (const float*)d_in[7];
    const float* proj_b = (const float*)d_in[8];
    const float* pp_w   = (const float*)d_in[9];
    const float* pp_b   = (const float*)d_in[10];
    const float* ln1_g  = (const float*)d_in[11];
    const float* ln1_b  = (const float*)d_in[12];
    const float* l1_w   = (const float*)d_in[13];
    const float* l1_b   = (const float*)d_in[14];
    const float* ln2_g  = (const float*)d_in[15];
    const float* ln2_b  = (const float*)d_in[16];
    const float* l2_w   = (const float*)d_in[17];
    const float* l2_b   = (const float*)d_in[18];
    const float* ln3_g  = (const float*)d_in[19];
    const float* ln3_b  = (const float*)d_in[20];
    const float* l3_w   = (const float*)d_in[21];
    const float* l3_b   = (const float*)d_in[22];
    (void)in_sizes; (void)n_in; (void)out_size;

    int gsmem = 2 * GSW_STAGE * (int)sizeof(uint32_t);   // 65536
    int asmem = A_TOT * (int)sizeof(uint32_t);           // 81920
    static int attr_done = 0;
    if (!attr_done) {
        cudaFuncSetAttribute(gemm_qkv, cudaFuncAttributeMaxDynamicSharedMemorySize, gsmem);
        cudaFuncSetAttribute(gemm_proj, cudaFuncAttributeMaxDynamicSharedMemorySize, gsmem);
        cudaFuncSetAttribute(attn_kernel, cudaFuncAttributeMaxDynamicSharedMemorySize, asmem);
        attr_done = 1;
    }

    conv_w_kernel<<<512, 256>>>(q_w, kv_w, proj_w, q_b);
    pos_mlp_kernel<<<4, 256>>>(pp_w, pp_b, ln1_g, ln1_b, l1_w, l1_b,
                               ln2_g, ln2_b, l2_w, l2_b, ln3_g, ln3_b, l3_w, l3_b);
    rpb_fill_kernel<<<NHEAD * NTOK * NTOK / 256, 256>>>();

    gemm_qkv<<<dim3(6, 512), 256, gsmem>>>(q, k, kv_b);
    attn_kernel<<<dim3(2, NHEAD, BATCH), 256, asmem>>>(mask);
    gemm_proj<<<dim3(2, 512), 256, gsmem>>>(proj_b, (float*)d_out);
}